// round 17
// baseline (speedup 1.0000x reference)
#include <cuda_runtime.h>
#include <cuda_fp16.h>
#include <math.h>
#include <stdint.h>

// Problem constants
#define SEQ     8192
#define BATCH   2
#define MTOT    (BATCH * SEQ)   // 16384
#define HIDDEN  768
#define KV      256
#define DMAX    7
#define NSM     148

// Scratch (static __device__ — no runtime allocation allowed)
__device__ float g_e[DMAX + 1];
__device__ __align__(16) __half g_vh[MTOT * KV];         // gemm1 out (fp16)
__device__ __align__(16) __half g_ah[MTOT * KV];         // smooth out (fp16)
__device__ __align__(16) __half g_wvh[KV * HIDDEN];      // Wv in fp16
__device__ __align__(16) __half g_woh[HIDDEN * KV];      // Wo in fp16

// ---------------------------------------------------------------------------
// helpers
// ---------------------------------------------------------------------------
__device__ __forceinline__ uint32_t smem_u32(const void* p) {
    uint32_t a;
    asm("{ .reg .u64 t; cvta.to.shared.u64 t, %1; cvt.u32.u64 %0, t; }"
        : "=r"(a) : "l"(p));
    return a;
}

__device__ __forceinline__ void ldsm4(uint32_t* r, uint32_t addr) {
    asm volatile("ldmatrix.sync.aligned.m8n8.x4.shared.b16 {%0,%1,%2,%3}, [%4];"
        : "=r"(r[0]), "=r"(r[1]), "=r"(r[2]), "=r"(r[3]) : "r"(addr));
}

__device__ __forceinline__ void mma_f16(float* d, const uint32_t* a,
                                        const uint32_t* b) {
    asm volatile(
        "mma.sync.aligned.m16n8k16.row.col.f32.f16.f16.f32 "
        "{%0,%1,%2,%3}, {%4,%5,%6,%7}, {%8,%9}, {%0,%1,%2,%3};"
        : "+f"(d[0]), "+f"(d[1]), "+f"(d[2]), "+f"(d[3])
        : "r"(a[0]), "r"(a[1]), "r"(a[2]), "r"(a[3]), "r"(b[0]), "r"(b[1]));
}

#define CP_ASYNC16(dst, src) \
    asm volatile("cp.async.cg.shared.global [%0], [%1], 16;" \
                 :: "r"(dst), "l"(src) : "memory")
#define CP_COMMIT() asm volatile("cp.async.commit_group;" ::: "memory")
#define CP_WAIT1()  asm volatile("cp.async.wait_group 1;" ::: "memory")
#define CP_WAIT0()  asm volatile("cp.async.wait_group 0;" ::: "memory")

// fp16 tiles: BK=64 -> 128B rows, 8-group XOR swizzle (conflict-free ldmatrix)
__device__ __forceinline__ uint32_t swz(int row, int kg) {
    return (uint32_t)(row * 128) + ((uint32_t)((kg ^ row) & 7) << 4);
}

// ===========================================================================
// GEMM2 (R14-frozen): fp16 in, fp32 out; 256x128 tile, 512 thr, BK=64,
// 3-stage cp.async (WAIT1), fragment double-buffer, persistent grid.
// ===========================================================================
#define G2_ASZ   (256 * 128)              // 32768
#define G2_BSZ   (128 * 128)              // 16384
#define G2_STG   (G2_ASZ + G2_BSZ)        // 49152
#define G2_NSTG  3

__global__ __launch_bounds__(512, 1) void gemm2_fp16(
    const __half* __restrict__ A, const __half* __restrict__ B,
    float* __restrict__ C, int M, int N, int K)
{
    extern __shared__ char dynsmem[];
    const uint32_t sb = (smem_u32(dynsmem) + 127u) & ~127u;

    const int tid  = threadIdx.x;
    const int wid  = tid >> 5;
    const int lane = tid & 31;
    const int NC   = K >> 6;
    const int nTilesN = N >> 7;
    const int nTiles  = (M >> 8) * nTilesN;

    const int warpM = (wid >> 2) * 64;
    const int warpN = (wid & 3) * 32;

    const int ra = tid >> 1, ha = tid & 1;     // A: 2 thr/row, 4x16B
    const int rb = tid >> 2, qb = tid & 3;     // B: 4 thr/row, 2x16B
    uint32_t dAo[4], dBo[2];
#pragma unroll
    for (int i = 0; i < 4; ++i) dAo[i] = swz(ra, ha * 4 + i);
#pragma unroll
    for (int i = 0; i < 2; ++i) dBo[i] = swz(rb, qb * 2 + i);

    const int laRow = warpM + (lane & 15);
    const int laKg  = lane >> 4;
    const int lbRow = warpN + (lane & 7) + ((lane & 16) >> 1);
    const int lbKg  = (lane >> 3) & 1;

#define G2_ISSUE(stg, kt)                                                 \
    do {                                                                  \
        uint32_t bs = sb + (uint32_t)(stg) * G2_STG;                      \
        const __half* pa = gA + (kt);                                     \
        const __half* pb = gB + (kt);                                     \
        CP_ASYNC16(bs + dAo[0], pa);                                      \
        CP_ASYNC16(bs + dAo[1], pa + 8);                                  \
        CP_ASYNC16(bs + dAo[2], pa + 16);                                 \
        CP_ASYNC16(bs + dAo[3], pa + 24);                                 \
        CP_ASYNC16(bs + G2_ASZ + dBo[0], pb);                             \
        CP_ASYNC16(bs + G2_ASZ + dBo[1], pb + 8);                         \
        CP_COMMIT();                                                      \
    } while (0)

    for (int t = blockIdx.x; t < nTiles; t += gridDim.x) {
        const int bm = (t / nTilesN) * 256;
        const int bn = (t - (t / nTilesN) * nTilesN) * 128;

        const __half* gA = A + (size_t)(bm + ra) * K + ha * 32;
        const __half* gB = B + (size_t)(bn + rb) * K + qb * 16;

        float acc[4][4][4];
#pragma unroll
        for (int i = 0; i < 4; ++i)
#pragma unroll
            for (int j = 0; j < 4; ++j)
#pragma unroll
                for (int q = 0; q < 4; ++q) acc[i][j][q] = 0.f;

        G2_ISSUE(0, 0);
        G2_ISSUE(1, 64);

        int stage = 0;
        for (int c = 0; c < NC; ++c) {
            CP_WAIT1();
            __syncthreads();

            if (c + 2 < NC) {
                int ns = stage + 2; if (ns >= G2_NSTG) ns -= G2_NSTG;
                G2_ISSUE(ns, (c + 2) * 64);
            }

            const uint32_t sA = sb + (uint32_t)stage * G2_STG;
            const uint32_t sB = sA + G2_ASZ;

            uint32_t af[2][4][4], bf[2][2][4];
#pragma unroll
            for (int mt = 0; mt < 4; ++mt)
                ldsm4(af[0][mt], sA + swz(laRow + mt * 16, laKg));
            ldsm4(bf[0][0], sB + swz(lbRow,      lbKg));
            ldsm4(bf[0][1], sB + swz(lbRow + 16, lbKg));

#pragma unroll
            for (int ks = 0; ks < 4; ++ks) {
                const int cur = ks & 1;
                if (ks < 3) {
                    const int kg = 2 * (ks + 1);
#pragma unroll
                    for (int mt = 0; mt < 4; ++mt)
                        ldsm4(af[cur ^ 1][mt],
                              sA + swz(laRow + mt * 16, kg + laKg));
                    ldsm4(bf[cur ^ 1][0], sB + swz(lbRow,      kg + lbKg));
                    ldsm4(bf[cur ^ 1][1], sB + swz(lbRow + 16, kg + lbKg));
                }
#pragma unroll
                for (int mt = 0; mt < 4; ++mt)
#pragma unroll
                    for (int nt = 0; nt < 4; ++nt)
                        mma_f16(acc[mt][nt], af[cur][mt],
                                &bf[cur][nt >> 1][(nt & 1) * 2]);
            }

            if (++stage >= G2_NSTG) stage = 0;
        }
        CP_WAIT0();

#pragma unroll
        for (int mt = 0; mt < 4; ++mt) {
#pragma unroll
            for (int nt = 0; nt < 4; ++nt) {
                int row = bm + warpM + mt * 16 + (lane >> 2);
                int col = bn + warpN + nt * 8 + (lane & 3) * 2;
                float2 v0 = make_float2(acc[mt][nt][0], acc[mt][nt][1]);
                float2 v1 = make_float2(acc[mt][nt][2], acc[mt][nt][3]);
                *reinterpret_cast<float2*>(C + (size_t)row * N + col) = v0;
                *reinterpret_cast<float2*>(C + (size_t)(row + 8) * N + col) = v1;
            }
        }
        __syncthreads();
    }
#undef G2_ISSUE
}

// ===========================================================================
// GEMM1 with in-kernel A conversion: A = x (fp32), B = Wv (fp16), out fp16.
// 256x128 tile, 512 thr, BK=64. 2-stage cp.async (A fp32 64KB + B 16KB per
// stage) + single A16 convert buffer. Per chunk: wait0/sync -> refill ->
// convert A32->A16 (flat LDS.128 + cvt + STS.64, conflict-free) -> sync ->
// ldmatrix/mma (identical inner loop). Conversion instrs hide in the idle
// issue slots of the HMMA throughput wall.
// ===========================================================================
#define G1_A32S  (256 * 64 * 4)           // 65536 per stage
#define G1_B16S  (128 * 128)              // 16384 per stage
#define G1_OFF_B (2 * G1_A32S)            // 131072
#define G1_OFF_A16 (G1_OFF_B + 2 * G1_B16S)   // 163840
#define G1_SMEM  (G1_OFF_A16 + 256 * 128 + 128) // 196736

__global__ __launch_bounds__(512, 1) void gemm1_cvt(
    const float* __restrict__ A, const __half* __restrict__ B,
    __half* __restrict__ C, int M, int N, int K)
{
    extern __shared__ char dynsmem[];
    const uint32_t sb = (smem_u32(dynsmem) + 127u) & ~127u;

    const int tid  = threadIdx.x;
    const int wid  = tid >> 5;
    const int lane = tid & 31;
    const int NC   = K >> 6;                 // 12
    const int nTilesN = N >> 7;              // 2
    const int nTiles  = (M >> 8) * nTilesN;  // 128

    const int warpM = (wid >> 2) * 64;
    const int warpN = (wid & 3) * 32;

    // A32 cp.async: 2 thr/row, thread covers 32 floats = 8x16B, flat layout
    const int ra = tid >> 1, ha = tid & 1;
    const uint32_t dA32 = (uint32_t)tid * 128u;   // = ra*256 + ha*128
    // B fp16: 4 thr/row, 2x16B, swizzled
    const int rb = tid >> 2, qb = tid & 3;
    uint32_t dBo[2];
#pragma unroll
    for (int i = 0; i < 2; ++i) dBo[i] = swz(rb, qb * 2 + i);

    const int laRow = warpM + (lane & 15);
    const int laKg  = lane >> 4;
    const int lbRow = warpN + (lane & 7) + ((lane & 16) >> 1);
    const int lbKg  = (lane >> 3) & 1;
    const uint32_t A16 = sb + G1_OFF_A16;

#define G1_ISSUE(stg, kt)                                                 \
    do {                                                                  \
        uint32_t aB = sb + (uint32_t)(stg) * G1_A32S + dA32;              \
        uint32_t bB = sb + G1_OFF_B + (uint32_t)(stg) * G1_B16S;          \
        const float* pa = gA + (kt);                                      \
        _Pragma("unroll")                                                 \
        for (int i = 0; i < 8; ++i) CP_ASYNC16(aB + 16 * i, pa + 4 * i);  \
        const __half* pb = gB + (kt);                                     \
        CP_ASYNC16(bB + dBo[0], pb);                                      \
        CP_ASYNC16(bB + dBo[1], pb + 8);                                  \
        CP_COMMIT();                                                      \
    } while (0)

    for (int t = blockIdx.x; t < nTiles; t += gridDim.x) {
        const int bm = (t / nTilesN) * 256;
        const int bn = (t - (t / nTilesN) * nTilesN) * 128;

        const float*  gA = A + (size_t)(bm + ra) * K + ha * 32;
        const __half* gB = B + (size_t)(bn + rb) * K + qb * 16;

        float acc[4][4][4];
#pragma unroll
        for (int i = 0; i < 4; ++i)
#pragma unroll
            for (int j = 0; j < 4; ++j)
#pragma unroll
                for (int q = 0; q < 4; ++q) acc[i][j][q] = 0.f;

        G1_ISSUE(0, 0);

        for (int c = 0; c < NC; ++c) {
            CP_WAIT0();
            __syncthreads();   // chunk c data ready + A16 reads of c-1 done

            if (c + 1 < NC) G1_ISSUE((c + 1) & 1, (c + 1) * 64);

            // convert A32 (flat) -> A16 (swizzled); conflict-free patterns
            {
                const uint32_t a32 = sb + (uint32_t)(c & 1) * G1_A32S;
#pragma unroll
                for (int j = 0; j < 8; ++j) {
                    int f = tid + 512 * j;          // float4 index 0..4095
                    float4 v;
                    asm volatile("ld.shared.v4.f32 {%0,%1,%2,%3}, [%4];"
                        : "=f"(v.x), "=f"(v.y), "=f"(v.z), "=f"(v.w)
                        : "r"(a32 + (uint32_t)f * 16u));
                    __half2 h0 = __floats2half2_rn(v.x, v.y);
                    __half2 h1 = __floats2half2_rn(v.z, v.w);
                    uint32_t u0 = *reinterpret_cast<uint32_t*>(&h0);
                    uint32_t u1 = *reinterpret_cast<uint32_t*>(&h1);
                    int row = f >> 4;
                    int kg  = (f & 15) >> 1;
                    uint32_t dst = A16 + swz(row, kg) + (uint32_t)(f & 1) * 8u;
                    asm volatile("st.shared.v2.b32 [%0], {%1,%2};"
                        :: "r"(dst), "r"(u0), "r"(u1) : "memory");
                }
            }
            __syncthreads();   // A16 ready for ldmatrix

            const uint32_t sB = sb + G1_OFF_B + (uint32_t)(c & 1) * G1_B16S;

            uint32_t af[2][4][4], bf[2][2][4];
#pragma unroll
            for (int mt = 0; mt < 4; ++mt)
                ldsm4(af[0][mt], A16 + swz(laRow + mt * 16, laKg));
            ldsm4(bf[0][0], sB + swz(lbRow,      lbKg));
            ldsm4(bf[0][1], sB + swz(lbRow + 16, lbKg));

#pragma unroll
            for (int ks = 0; ks < 4; ++ks) {
                const int cur = ks & 1;
                if (ks < 3) {
                    const int kg = 2 * (ks + 1);
#pragma unroll
                    for (int mt = 0; mt < 4; ++mt)
                        ldsm4(af[cur ^ 1][mt],
                              A16 + swz(laRow + mt * 16, kg + laKg));
                    ldsm4(bf[cur ^ 1][0], sB + swz(lbRow,      kg + lbKg));
                    ldsm4(bf[cur ^ 1][1], sB + swz(lbRow + 16, kg + lbKg));
                }
#pragma unroll
                for (int mt = 0; mt < 4; ++mt)
#pragma unroll
                    for (int nt = 0; nt < 4; ++nt)
                        mma_f16(acc[mt][nt], af[cur][mt],
                                &bf[cur][nt >> 1][(nt & 1) * 2]);
            }
        }
        CP_WAIT0();

        // epilogue: fp16 out
#pragma unroll
        for (int mt = 0; mt < 4; ++mt) {
#pragma unroll
            for (int nt = 0; nt < 4; ++nt) {
                int row = bm + warpM + mt * 16 + (lane >> 2);
                int col = bn + warpN + nt * 8 + (lane & 3) * 2;
                __half2 h0 = __floats2half2_rn(acc[mt][nt][0], acc[mt][nt][1]);
                __half2 h1 = __floats2half2_rn(acc[mt][nt][2], acc[mt][nt][3]);
                *reinterpret_cast<__half2*>(C + (size_t)row * N + col) = h0;
                *reinterpret_cast<__half2*>(C + (size_t)(row + 8) * N + col) = h1;
            }
        }
        __syncthreads();
    }
#undef G1_ISSUE
}

// ---------------------------------------------------------------------------
// Kernel 0: prologue. Block 0: coefficients. Blocks 1..768: weights -> fp16.
// ---------------------------------------------------------------------------
#define WBLK (KV * HIDDEN / 256)            // 768

__global__ void pre_kernel(const float* __restrict__ Wv,
                           const float* __restrict__ Wo) {
    const int b = blockIdx.x;
    if (b == 0) {
        __shared__ float warp_sum[8];
        const int t = threadIdx.x;
        const int lane = t & 31, warp = t >> 5;
        const float cc = -logf(10000.0f) / 384.0f;
        for (int d = 0; d <= DMAX; ++d) {
            float val = 0.f;
            for (int j = t; j < 384; j += 256)
                val += cosf((float)d * __expf(cc * (float)j));
#pragma unroll
            for (int o = 16; o; o >>= 1)
                val += __shfl_xor_sync(0xffffffffu, val, o);
            if (lane == 0) warp_sum[warp] = val;
            __syncthreads();
            if (t == 0) {
                float w = 0.f;
#pragma unroll
                for (int i = 0; i < 8; ++i) w += warp_sum[i];
                g_e[d] = expf(w - 384.0f);
            }
            __syncthreads();
        }
    } else {
        int i = (b - 1) * 256 + threadIdx.x;
        g_wvh[i] = __float2half_rn(Wv[i]);
        g_woh[i] = __float2half_rn(Wo[i]);
    }
}

// ---------------------------------------------------------------------------
// Kernel 2: softmax == normalized 15-tap convolution along seq (fp16 IO).
// Sliding window: 4 consecutive rows x 4 cols per thread; fp32 accumulate.
// ---------------------------------------------------------------------------
__global__ __launch_bounds__(256) void smooth_kernel() {
    const int NCG = KV / 4;                       // 64 col-groups of 4
    int idx = blockIdx.x * blockDim.x + threadIdx.x;
    if (idx >= (MTOT / 4) * NCG) return;
    const int mg = idx >> 6;
    const int c4 = (idx & 63) * 4;
    const int m0 = mg << 2;
    const int s0 = m0 & (SEQ - 1);

    float earr[15];
#pragma unroll
    for (int t = 0; t < 15; ++t) earr[t] = g_e[t < 7 ? 7 - t : t - 7];

    uint2 w[18];
#pragma unroll
    for (int j = 0; j < 18; ++j) {
        int s = s0 - 7 + j;
        if (s >= 0 && s < SEQ)
            w[j] = *reinterpret_cast<const uint2*>(
                g_vh + (size_t)(m0 - 7 + j) * KV + c4);
        else
            w[j] = make_uint2(0u, 0u);
    }

#pragma unroll
    for (int i = 0; i < 4; ++i) {
        const int s = s0 + i;
        float acc[4] = {0.f, 0.f, 0.f, 0.f};
#pragma unroll
        for (int t = 0; t < 15; ++t) {
            const float e = earr[t];
            const uint32_t* uw = reinterpret_cast<const uint32_t*>(&w[i + t]);
#pragma unroll
            for (int p = 0; p < 2; ++p) {
                __half2 hh;
                *reinterpret_cast<uint32_t*>(&hh) = uw[p];
                float2 f = __half22float2(hh);
                acc[p * 2 + 0] += e * f.x;
                acc[p * 2 + 1] += e * f.y;
            }
        }
        float z = 1.0f;
#pragma unroll
        for (int d = 1; d <= DMAX; ++d) {
            if (s >= d)       z += g_e[d];
            if (s + d < SEQ)  z += g_e[d];
        }
        const float inv = 1.0f / z;
        __half2 o0 = __floats2half2_rn(acc[0] * inv, acc[1] * inv);
        __half2 o1 = __floats2half2_rn(acc[2] * inv, acc[3] * inv);
        uint2 o;
        o.x = *reinterpret_cast<uint32_t*>(&o0);
        o.y = *reinterpret_cast<uint32_t*>(&o1);
        *reinterpret_cast<uint2*>(g_ah + (size_t)(m0 + i) * KV + c4) = o;
    }
}

// ---------------------------------------------------------------------------
// Launch
// ---------------------------------------------------------------------------
extern "C" void kernel_launch(void* const* d_in, const int* in_sizes, int n_in,
                              void* d_out, int out_size) {
    const float* x  = (const float*)d_in[0];
    // d_in[1] = Wq, d_in[2] = Wk are dead (rope ignores its input)
    const float* Wv = (const float*)d_in[3];
    const float* Wo = (const float*)d_in[4];
    float* out = (float*)d_out;

    __half* vh_buf; cudaGetSymbolAddress((void**)&vh_buf, g_vh);
    __half* ah_buf; cudaGetSymbolAddress((void**)&ah_buf, g_ah);
    __half* wv_buf; cudaGetSymbolAddress((void**)&wv_buf, g_wvh);
    __half* wo_buf; cudaGetSymbolAddress((void**)&wo_buf, g_woh);

    const int SM1 = G1_SMEM;                       // ~192 KB
    const int SM2 = G2_NSTG * G2_STG + 128;        // ~144 KB
    cudaFuncSetAttribute(gemm1_cvt,
                         cudaFuncAttributeMaxDynamicSharedMemorySize, SM1);
    cudaFuncSetAttribute(gemm2_fp16,
                         cudaFuncAttributeMaxDynamicSharedMemorySize, SM2);

    // 0) coefficients + weight conversion only (x converted inside gemm1)
    pre_kernel<<<1 + WBLK, 256>>>(Wv, Wo);

    // 1) v = x(fp32) @ Wv^T -> fp16  (128 tiles)
    gemm1_cvt<<<128, 512, SM1>>>(x, wv_buf, vh_buf, MTOT, KV, HIDDEN);

    // 2) softmax(attn) @ v == normalized 15-tap convolution (fp16 -> fp16)
    {
        int n = (MTOT / 4) * (KV / 4);
        smooth_kernel<<<(n + 255) / 256, 256>>>();
    }

    // 3) out = a @ Wo^T -> fp32 (384 tiles, persistent over 148 CTAs)
    gemm2_fp16<<<NSM, 512, SM2>>>(ah_buf, wo_buf, out, MTOT, HIDDEN, KV);
}